// round 16
// baseline (speedup 1.0000x reference)
#include <cuda_runtime.h>
#include <math.h>

#define SAMPLE_RATE 44100.0f
#define R_PARAM 0.5f
#define F_PARAM 1000.0f

// FINAL: single fused kernel, NO barrier / NO smem / NO call.
//
// The benchmark steady state is HBM-bound: 201MB irreducible I/O per replay
// at ~5.7TB/s sustained mixed-R/W == ~35.3us total, independent of isolated
// kernel time (writeback drain overlaps the next replay). This configuration
// reached that floor; all shape/cache/occupancy/persistence variants were
// neutral or worse over 8 rounds of measurement.
//
// Every thread redundantly computes the fused affine map
//     x_n = M x_n1 + va u_n + vb u_n1,   y = gain * x_n[3]
// via a CLOSED-FORM inverse of L = I - (k/2)*alpha*A:
//     L = [[ d, 0, 0, e],
//          [-a, d, 0, 0],
//          [ 0,-a, d, 0],
//          [ 0, 0,-a, d]],  a = (k/2)*alpha*w, d = 1+a, e = 2*a*gr
// (forward substitution + one determinant -> Linv in ~40 flops; then
//  M = Linv @ F with F = I + (k/2)(2-alpha)A, 8 nonzeros; va, vb are
//  scalar multiples of Linv[:,0] since input vector B has one nonzero).
// The ~80-flop chain hides entirely under the batched data-load latency.
//
// Each thread handles 4 samples strided by 32 within its warp:
//     sample(s) = warp*128 + s*32 + lane
// -> every LDG/STG instruction is perfectly coalesced (x: full 512B of lines
//    per instruction; u/u1/y: one full 128B line per instruction).
// Output layout (out_size = 6*B floats): [0,B) y | [B,5B) x | [5B,6B) u
__global__ __launch_bounds__(256, 4)
void moog_fused_kernel(const float* __restrict__ u,
                       const float4* __restrict__ x1,
                       const float* __restrict__ u1,
                       const float* __restrict__ p_gf,
                       const float* __restrict__ p_gr,
                       const float* __restrict__ p_gain,
                       const float* __restrict__ p_alpha,
                       float* __restrict__ out, int B) {
    int tid = blockIdx.x * blockDim.x + threadIdx.x;
    int warp = tid >> 5;
    int lane = tid & 31;
    int base = warp * 128 + lane;            // sample index for s=0
    if (base + 96 >= B) return;              // B is a multiple of 128

    // ---- Issue all data loads FIRST (independent of constants) ----
    float4 xv[4];
    float uu[4], uu1[4];
#pragma unroll
    for (int s = 0; s < 4; s++) {
        int idx = base + 32 * s;
        xv[s]  = x1[idx];
        uu[s]  = u[idx];
        uu1[s] = u1[idx];
    }

    // ---- Broadcast scalar params (one 32B sector, L2-resident) ----
    float GF = p_gf[0];
    float GR = p_gr[0];
    float gain = p_gain[0];
    float AL = p_alpha[0];

    // ---- Closed-form fused constants (per-thread, ~80 flops) ----
    float k  = 1.0f / SAMPLE_RATE;
    float w  = 2.0f * 3.14159265358979323846f * GF * F_PARAM;
    float a  = 0.5f * k * AL * w;            // (k/2)*alpha*w
    float d  = 1.0f + a;
    float e  = 2.0f * a * GR;                // 4*(k/2)alpha*w*gr*R, R=0.5
    float cp = 0.5f * k * (2.0f - AL) * w;   // (k/2)(2-alpha)*w
    float f  = 1.0f - cp;                    // F diag
    float h  = cp;                           // F subdiag
    float g  = 2.0f * cp * GR;               // -F[0][3]
    float ba0  = a;                          // (k w/2)*alpha
    float bma0 = 0.5f * k * w * (1.0f - 0.5f * AL);

    float rd  = __frcp_rn(d);
    float d2  = d * d;
    float d3  = d2 * d;
    float det = fmaf(e * a, a * a, d2 * d2); // d^4 + e*a^3
    float rD  = __frcp_rn(det);
    float ard = a * rd;

    // Linv columns (L{row}{col})
    float L00 = d3 * rD;
    float L10 = ard * L00;
    float L20 = ard * L10;
    float L30 = ard * L20;

    float L01 = -(e * a) * a * rD;
    float L11 = fmaf(ard, L01, rd);
    float L21 = ard * L11;
    float L31 = ard * L21;

    float L02 = -(e * a) * d * rD;
    float L12 = ard * L02;
    float L22 = fmaf(ard, L12, rd);
    float L32 = ard * L22;

    float L03 = -e * d2 * rD;
    float L13 = ard * L03;
    float L23 = ard * L13;
    float L33 = fmaf(ard, L23, rd);

    // M rows: Mc0=c0*f+c1*h, Mc1=c1*f+c2*h, Mc2=c2*f+c3*h, Mc3=c3*f-c0*g
    float4 m0 = make_float4(fmaf(L00, f, L01 * h), fmaf(L01, f, L02 * h),
                            fmaf(L02, f, L03 * h), fmaf(L03, f, -L00 * g));
    float4 m1 = make_float4(fmaf(L10, f, L11 * h), fmaf(L11, f, L12 * h),
                            fmaf(L12, f, L13 * h), fmaf(L13, f, -L10 * g));
    float4 m2 = make_float4(fmaf(L20, f, L21 * h), fmaf(L21, f, L22 * h),
                            fmaf(L22, f, L23 * h), fmaf(L23, f, -L20 * g));
    float4 m3 = make_float4(fmaf(L30, f, L31 * h), fmaf(L31, f, L32 * h),
                            fmaf(L32, f, L33 * h), fmaf(L33, f, -L30 * g));
    float4 va = make_float4(ba0 * L00, ba0 * L10, ba0 * L20, ba0 * L30);
    float4 vb = make_float4(bma0 * L00, bma0 * L10, bma0 * L20, bma0 * L30);

    float4* x_out = (float4*)(out + (size_t)B);
    float*  u_out = out + (size_t)5 * B;
    float*  y_out = out;

#pragma unroll
    for (int s = 0; s < 4; s++) {
        int idx = base + 32 * s;
        float4 x = xv[s];
        float x0n = fmaf(m0.x, x.x, fmaf(m0.y, x.y, fmaf(m0.z, x.z,
                    fmaf(m0.w, x.w, fmaf(va.x, uu[s], vb.x * uu1[s])))));
        float x1n = fmaf(m1.x, x.x, fmaf(m1.y, x.y, fmaf(m1.z, x.z,
                    fmaf(m1.w, x.w, fmaf(va.y, uu[s], vb.y * uu1[s])))));
        float x2n = fmaf(m2.x, x.x, fmaf(m2.y, x.y, fmaf(m2.z, x.z,
                    fmaf(m2.w, x.w, fmaf(va.z, uu[s], vb.z * uu1[s])))));
        float x3n = fmaf(m3.x, x.x, fmaf(m3.y, x.y, fmaf(m3.z, x.z,
                    fmaf(m3.w, x.w, fmaf(va.w, uu[s], vb.w * uu1[s])))));
        x_out[idx] = make_float4(x0n, x1n, x2n, x3n);
        y_out[idx] = gain * x3n;
        u_out[idx] = uu[s];
    }
}

extern "C" void kernel_launch(void* const* d_in, const int* in_sizes, int n_in,
                              void* d_out, int out_size) {
    const float* u_n   = (const float*)d_in[0];
    const float* x_n1  = (const float*)d_in[1];
    const float* u_n1  = (const float*)d_in[2];
    const float* gf    = (const float*)d_in[3];
    const float* gr    = (const float*)d_in[4];
    const float* gain  = (const float*)d_in[5];
    const float* alpha = (const float*)d_in[6];
    float* out = (float*)d_out;

    int B = in_sizes[0];

    int threads = 256;
    int total_threads = B / 4;           // 4 samples per thread
    int blocks = (total_threads + threads - 1) / threads;
    moog_fused_kernel<<<blocks, threads>>>(u_n, (const float4*)x_n1, u_n1,
                                           gf, gr, gain, alpha, out, B);
}

// round 17
// speedup vs baseline: 1.0146x; 1.0146x over previous
#include <cuda_runtime.h>
#include <math.h>

#define SAMPLE_RATE 44100.0f
#define R_PARAM 0.5f
#define F_PARAM 1000.0f

// Single fused kernel, NO barrier / NO smem / NO call.
// R8 proven shape + per-stream GROUPED stores (x then y then u) so each warp
// emits longer same-stream write runs to the memory controller.
//
// Steady state is HBM-bound: 201MB irreducible I/O per replay at ~5.7TB/s
// sustained mixed-R/W ~= 35.3us total, independent of isolated kernel time.
//
// Every thread redundantly computes the fused affine map
//     x_n = M x_n1 + va u_n + vb u_n1,   y = gain * x_n[3]
// via a CLOSED-FORM inverse of L = I - (k/2)*alpha*A:
//     L = [[ d, 0, 0, e],
//          [-a, d, 0, 0],
//          [ 0,-a, d, 0],
//          [ 0, 0,-a, d]],  a = (k/2)*alpha*w, d = 1+a, e = 2*a*gr
// (forward substitution + one determinant -> Linv in ~40 flops; then
//  M = Linv @ F with F = I + (k/2)(2-alpha)A, 8 nonzeros; va, vb are
//  scalar multiples of Linv[:,0] since input vector B has one nonzero).
// The ~80-flop chain hides entirely under the batched data-load latency.
//
// Each thread handles 4 samples strided by 32 within its warp:
//     sample(s) = warp*128 + s*32 + lane
// -> every LDG/STG instruction is perfectly coalesced (x: full 512B of lines
//    per instruction; u/u1/y: one full 128B line per instruction).
// Output layout (out_size = 6*B floats): [0,B) y | [B,5B) x | [5B,6B) u
__global__ __launch_bounds__(256, 4)
void moog_fused_kernel(const float* __restrict__ u,
                       const float4* __restrict__ x1,
                       const float* __restrict__ u1,
                       const float* __restrict__ p_gf,
                       const float* __restrict__ p_gr,
                       const float* __restrict__ p_gain,
                       const float* __restrict__ p_alpha,
                       float* __restrict__ out, int B) {
    int tid = blockIdx.x * blockDim.x + threadIdx.x;
    int warp = tid >> 5;
    int lane = tid & 31;
    int base = warp * 128 + lane;            // sample index for s=0
    if (base + 96 >= B) return;              // B is a multiple of 128

    // ---- Issue all data loads FIRST (independent of constants) ----
    float4 xv[4];
    float uu[4], uu1[4];
#pragma unroll
    for (int s = 0; s < 4; s++) {
        int idx = base + 32 * s;
        xv[s]  = x1[idx];
        uu[s]  = u[idx];
        uu1[s] = u1[idx];
    }

    // ---- Broadcast scalar params (one 32B sector, L2-resident) ----
    float GF = p_gf[0];
    float GR = p_gr[0];
    float gain = p_gain[0];
    float AL = p_alpha[0];

    // ---- Closed-form fused constants (per-thread, ~80 flops) ----
    float k  = 1.0f / SAMPLE_RATE;
    float w  = 2.0f * 3.14159265358979323846f * GF * F_PARAM;
    float a  = 0.5f * k * AL * w;            // (k/2)*alpha*w
    float d  = 1.0f + a;
    float e  = 2.0f * a * GR;                // 4*(k/2)alpha*w*gr*R, R=0.5
    float cp = 0.5f * k * (2.0f - AL) * w;   // (k/2)(2-alpha)*w
    float f  = 1.0f - cp;                    // F diag
    float h  = cp;                           // F subdiag
    float g  = 2.0f * cp * GR;               // -F[0][3]
    float ba0  = a;                          // (k w/2)*alpha
    float bma0 = 0.5f * k * w * (1.0f - 0.5f * AL);

    float rd  = __frcp_rn(d);
    float d2  = d * d;
    float d3  = d2 * d;
    float det = fmaf(e * a, a * a, d2 * d2); // d^4 + e*a^3
    float rD  = __frcp_rn(det);
    float ard = a * rd;

    // Linv columns (L{row}{col})
    float L00 = d3 * rD;
    float L10 = ard * L00;
    float L20 = ard * L10;
    float L30 = ard * L20;

    float L01 = -(e * a) * a * rD;
    float L11 = fmaf(ard, L01, rd);
    float L21 = ard * L11;
    float L31 = ard * L21;

    float L02 = -(e * a) * d * rD;
    float L12 = ard * L02;
    float L22 = fmaf(ard, L12, rd);
    float L32 = ard * L22;

    float L03 = -e * d2 * rD;
    float L13 = ard * L03;
    float L23 = ard * L13;
    float L33 = fmaf(ard, L23, rd);

    // M rows: Mc0=c0*f+c1*h, Mc1=c1*f+c2*h, Mc2=c2*f+c3*h, Mc3=c3*f-c0*g
    float4 m0 = make_float4(fmaf(L00, f, L01 * h), fmaf(L01, f, L02 * h),
                            fmaf(L02, f, L03 * h), fmaf(L03, f, -L00 * g));
    float4 m1 = make_float4(fmaf(L10, f, L11 * h), fmaf(L11, f, L12 * h),
                            fmaf(L12, f, L13 * h), fmaf(L13, f, -L10 * g));
    float4 m2 = make_float4(fmaf(L20, f, L21 * h), fmaf(L21, f, L22 * h),
                            fmaf(L22, f, L23 * h), fmaf(L23, f, -L20 * g));
    float4 m3 = make_float4(fmaf(L30, f, L31 * h), fmaf(L31, f, L32 * h),
                            fmaf(L32, f, L33 * h), fmaf(L33, f, -L30 * g));
    float4 va = make_float4(ba0 * L00, ba0 * L10, ba0 * L20, ba0 * L30);
    float4 vb = make_float4(bma0 * L00, bma0 * L10, bma0 * L20, bma0 * L30);

    float4* x_out = (float4*)(out + (size_t)B);
    float*  u_out = out + (size_t)5 * B;
    float*  y_out = out;

    // Compute all samples, then store grouped per output stream.
    float4 xo[4];
    float  yo[4];
#pragma unroll
    for (int s = 0; s < 4; s++) {
        float4 x = xv[s];
        float x0n = fmaf(m0.x, x.x, fmaf(m0.y, x.y, fmaf(m0.z, x.z,
                    fmaf(m0.w, x.w, fmaf(va.x, uu[s], vb.x * uu1[s])))));
        float x1n = fmaf(m1.x, x.x, fmaf(m1.y, x.y, fmaf(m1.z, x.z,
                    fmaf(m1.w, x.w, fmaf(va.y, uu[s], vb.y * uu1[s])))));
        float x2n = fmaf(m2.x, x.x, fmaf(m2.y, x.y, fmaf(m2.z, x.z,
                    fmaf(m2.w, x.w, fmaf(va.z, uu[s], vb.z * uu1[s])))));
        float x3n = fmaf(m3.x, x.x, fmaf(m3.y, x.y, fmaf(m3.z, x.z,
                    fmaf(m3.w, x.w, fmaf(va.w, uu[s], vb.w * uu1[s])))));
        xo[s] = make_float4(x0n, x1n, x2n, x3n);
        yo[s] = gain * x3n;
    }
#pragma unroll
    for (int s = 0; s < 4; s++) x_out[base + 32 * s] = xo[s];
#pragma unroll
    for (int s = 0; s < 4; s++) y_out[base + 32 * s] = yo[s];
#pragma unroll
    for (int s = 0; s < 4; s++) u_out[base + 32 * s] = uu[s];
}

extern "C" void kernel_launch(void* const* d_in, const int* in_sizes, int n_in,
                              void* d_out, int out_size) {
    const float* u_n   = (const float*)d_in[0];
    const float* x_n1  = (const float*)d_in[1];
    const float* u_n1  = (const float*)d_in[2];
    const float* gf    = (const float*)d_in[3];
    const float* gr    = (const float*)d_in[4];
    const float* gain  = (const float*)d_in[5];
    const float* alpha = (const float*)d_in[6];
    float* out = (float*)d_out;

    int B = in_sizes[0];

    int threads = 256;
    int total_threads = B / 4;           // 4 samples per thread
    int blocks = (total_threads + threads - 1) / threads;
    moog_fused_kernel<<<blocks, threads>>>(u_n, (const float4*)x_n1, u_n1,
                                           gf, gr, gain, alpha, out, B);
}